// round 6
// baseline (speedup 1.0000x reference)
#include <cuda_runtime.h>
#include <cuda_bf16.h>
#include <cstdint>

// Problem shape (fixed): B=4, T=2048, C=1024, H=16, D=64
#define B_   4
#define T_   2048
#define C_   1024
#define H_   16
#define D_   64
#define M_   (B_ * T_)      // 8192 rows
#define C3_  (3 * C_)       // 3072

// Scratch (allocation-free rule: __device__ globals)
__device__ float    g_qkv[(size_t)M_ * C3_];  // 96 MB, values tf32-rounded
__device__ float    g_y[(size_t)M_ * C_];     // 32 MB, values tf32-rounded
__device__ uint32_t g_xa[(size_t)M_ * C_];    // 32 MB, x as tf32 bits
__device__ uint32_t g_wa[(size_t)C_ * C3_];   // 12 MB, W_attn as tf32 bits
__device__ uint32_t g_wp[(size_t)C_ * C_];    //  4 MB, W_proj as tf32 bits

// Buffer selectors
#define U_XA 0
#define U_WA 1
#define U_WP 2
#define U_Y  3
#define D_QKV 0
#define D_EXT 1

__device__ __forceinline__ uint32_t* resolve_u(int sel) {
    if (sel == U_XA) return g_xa;
    if (sel == U_WA) return g_wa;
    if (sel == U_WP) return g_wp;
    return reinterpret_cast<uint32_t*>(g_y);
}

__device__ __forceinline__ void cp_async16(void* smem_dst, const void* gmem_src) {
    uint32_t s = (uint32_t)__cvta_generic_to_shared(smem_dst);
    asm volatile("cp.async.cg.shared.global [%0], [%1], 16;\n" :: "r"(s), "l"(gmem_src));
}
__device__ __forceinline__ void cp_async_commit() {
    asm volatile("cp.async.commit_group;\n");
}
__device__ __forceinline__ void cp_async_wait_all() {
    asm volatile("cp.async.wait_group 0;\n");
}
__device__ __forceinline__ uint32_t f2tf32(float x) {
    uint32_t u;
    asm("cvt.rna.tf32.f32 %0, %1;\n" : "=r"(u) : "f"(x));
    return u;
}
__device__ __forceinline__ void mma_tf32(float* c, const uint32_t* a,
                                         uint32_t b0, uint32_t b1) {
    asm volatile(
        "mma.sync.aligned.m16n8k8.row.col.f32.tf32.tf32.f32 "
        "{%0,%1,%2,%3}, {%4,%5,%6,%7}, {%8,%9}, {%0,%1,%2,%3};\n"
        : "+f"(c[0]), "+f"(c[1]), "+f"(c[2]), "+f"(c[3])
        : "r"(a[0]), "r"(a[1]), "r"(a[2]), "r"(a[3]), "r"(b0), "r"(b1));
}

// ---------------------------------------------------------------------------
// Boundary converter: f32 -> tf32 bits (rna). Vectorized float4 -> uint4.
// ---------------------------------------------------------------------------
template <int OSEL>
__global__ __launch_bounds__(256) void cvt_tf32_kernel(const float4* __restrict__ in, int n4)
{
    uint32_t* out = resolve_u(OSEL);
    int i = blockIdx.x * blockDim.x + threadIdx.x;
    if (i < n4) {
        float4 v = in[i];
        uint4 u;
        u.x = f2tf32(v.x); u.y = f2tf32(v.y);
        u.z = f2tf32(v.z); u.w = f2tf32(v.w);
        reinterpret_cast<uint4*>(out)[i] = u;
    }
}

// ---------------------------------------------------------------------------
// TF32 tensor-core GEMM + bias on pre-converted tf32-bit inputs (NO cvt in loop).
// out[M,N] = A[M,K] @ W[K,N] + bias[N].
// ROUND: epilogue stores tf32-rounded values (for qkv, consumed by attention).
// ---------------------------------------------------------------------------
#define BM 128
#define BN 128
#define BKT 16
#define A_STRIDE 20
#define B_STRIDE 136

template <int ASEL, int WSEL, int DSEL, bool ROUND>
__global__ __launch_bounds__(256) void gemm_tf32_kernel(
    const float* __restrict__ bias, float* __restrict__ out_ext,
    int K, int N)
{
    const uint32_t* A = resolve_u(ASEL);
    const uint32_t* W = resolve_u(WSEL);
    float* out = (DSEL == D_QKV) ? g_qkv : out_ext;

    __shared__ uint32_t As[2][BM][A_STRIDE];
    __shared__ uint32_t Bs[2][BKT][B_STRIDE];

    const int tid  = threadIdx.x;
    const int warp = tid >> 5;
    const int lane = tid & 31;
    const int gid  = lane >> 2;
    const int tq   = lane & 3;

    const int warp_m = warp & 1;
    const int warp_n = warp >> 1;

    const int m0 = blockIdx.y * BM;
    const int n0 = blockIdx.x * BN;

    const int a_row0 = tid >> 2;
    const int a_kc0  = (tid & 3) * 4;
    const int b_row0 = tid >> 5;
    const int b_col0 = (tid & 31) * 4;

    float acc[4][4][4];
#pragma unroll
    for (int i = 0; i < 4; i++)
#pragma unroll
        for (int j = 0; j < 4; j++)
#pragma unroll
            for (int r = 0; r < 4; r++) acc[i][j][r] = 0.f;

    const int NT = K / BKT;

    auto load_tile = [&](int kt, int buf) {
#pragma unroll
        for (int i = 0; i < 2; i++) {
            int row = a_row0 + i * 64;
            cp_async16(&As[buf][row][a_kc0],
                       A + (size_t)(m0 + row) * K + kt * BKT + a_kc0);
        }
#pragma unroll
        for (int i = 0; i < 2; i++) {
            int row = b_row0 + i * 8;
            cp_async16(&Bs[buf][row][b_col0],
                       W + (size_t)(kt * BKT + row) * N + n0 + b_col0);
        }
        cp_async_commit();
    };

    int buf = 0;
    load_tile(0, 0);

    for (int kt = 0; kt < NT; kt++) {
        cp_async_wait_all();
        __syncthreads();

        if (kt + 1 < NT) load_tile(kt + 1, buf ^ 1);

#pragma unroll
        for (int ks = 0; ks < BKT; ks += 8) {
            uint32_t af[4][4], bf[4][2];
#pragma unroll
            for (int mf = 0; mf < 4; mf++) {
                int mrow = warp_m * 64 + mf * 16;
                af[mf][0] = As[buf][mrow + gid    ][ks + tq    ];
                af[mf][1] = As[buf][mrow + gid + 8][ks + tq    ];
                af[mf][2] = As[buf][mrow + gid    ][ks + tq + 4];
                af[mf][3] = As[buf][mrow + gid + 8][ks + tq + 4];
            }
#pragma unroll
            for (int nf = 0; nf < 4; nf++) {
                int ncol = warp_n * 32 + nf * 8;
                bf[nf][0] = Bs[buf][ks + tq    ][ncol + gid];
                bf[nf][1] = Bs[buf][ks + tq + 4][ncol + gid];
            }
#pragma unroll
            for (int mf = 0; mf < 4; mf++)
#pragma unroll
                for (int nf = 0; nf < 4; nf++)
                    mma_tf32(acc[mf][nf], af[mf], bf[nf][0], bf[nf][1]);
        }
        buf ^= 1;
    }

#pragma unroll
    for (int nf = 0; nf < 4; nf++) {
        int colp = n0 + warp_n * 32 + nf * 8 + 2 * tq;
        float2 bb = *(const float2*)&bias[colp];
#pragma unroll
        for (int mf = 0; mf < 4; mf++) {
            int row0 = m0 + warp_m * 64 + mf * 16 + gid;
            float r00 = acc[mf][nf][0] + bb.x, r01 = acc[mf][nf][1] + bb.y;
            float r10 = acc[mf][nf][2] + bb.x, r11 = acc[mf][nf][3] + bb.y;
            if (ROUND) {
                r00 = __uint_as_float(f2tf32(r00));
                r01 = __uint_as_float(f2tf32(r01));
                r10 = __uint_as_float(f2tf32(r10));
                r11 = __uint_as_float(f2tf32(r11));
            }
            *(float2*)(out + (size_t)row0 * N + colp)       = make_float2(r00, r01);
            *(float2*)(out + (size_t)(row0 + 8) * N + colp) = make_float2(r10, r11);
        }
    }
}

// ---------------------------------------------------------------------------
// Tensor-core flash attention (causal). g_qkv values are ALREADY tf32-rounded,
// so Q/K/V feed raw bits to mma (truncation of rounded bits = identity).
// Output y written tf32-rounded so proj GEMM needs no cvt either.
// ---------------------------------------------------------------------------
#define AS_ 68   // padded stride: fragment LDS conflict-free

__global__ __launch_bounds__(128) void attn_tc_kernel()
{
    __shared__ uint32_t KPs[64][AS_];   // K tile (bits), then P tile
    __shared__ uint32_t Vs[64][AS_];    // V tile (bits)

    const int tid  = threadIdx.x;
    const int warp = tid >> 5;
    const int lane = tid & 31;
    const int gid  = lane >> 2;   // 0..7
    const int tq   = lane & 3;    // 0..3

    const int qt = gridDim.x - 1 - blockIdx.x;   // longest tiles first
    const int bh = blockIdx.y;
    const int b = bh >> 4, h = bh & 15;
    const int q0 = qt * 64;
    const int qrow = warp * 16;

    const int lrow = tid >> 4;         // 0..7
    const int lcol = (tid & 15) * 4;   // 0..60

    const float scale = 0.125f;        // exact power of 2: preserves tf32-ness
    const float* base = g_qkv + (size_t)(b * T_) * C3_ + h * D_;

    // ---- Stage Q (scaled) into KPs; values remain exactly tf32 ----
#pragma unroll
    for (int p = 0; p < 8; p++) {
        int row = lrow + p * 8;
        float4 v = *(const float4*)(base + (size_t)(q0 + row) * C3_ + lcol);
        KPs[row][lcol + 0] = __float_as_uint(v.x * scale);
        KPs[row][lcol + 1] = __float_as_uint(v.y * scale);
        KPs[row][lcol + 2] = __float_as_uint(v.z * scale);
        KPs[row][lcol + 3] = __float_as_uint(v.w * scale);
    }
    __syncthreads();

    uint32_t qa[8][4];
#pragma unroll
    for (int ch = 0; ch < 8; ch++) {
        qa[ch][0] = KPs[qrow + gid    ][ch * 8 + tq    ];
        qa[ch][1] = KPs[qrow + gid + 8][ch * 8 + tq    ];
        qa[ch][2] = KPs[qrow + gid    ][ch * 8 + tq + 4];
        qa[ch][3] = KPs[qrow + gid + 8][ch * 8 + tq + 4];
    }
    __syncthreads();

    float m_i[2] = {-1e30f, -1e30f};
    float l_i[2] = {0.f, 0.f};
    float o[8][4];
#pragma unroll
    for (int nf = 0; nf < 8; nf++)
#pragma unroll
        for (int r = 0; r < 4; r++) o[nf][r] = 0.f;

    for (int kt = 0; kt <= qt; kt++) {
        const int k0 = kt * 64;
        // ---- Load K and V tiles (raw bits; already tf32 values) ----
#pragma unroll
        for (int p = 0; p < 8; p++) {
            int row = lrow + p * 8;
            float4 kv = *(const float4*)(base + C_ + (size_t)(k0 + row) * C3_ + lcol);
            KPs[row][lcol + 0] = __float_as_uint(kv.x);
            KPs[row][lcol + 1] = __float_as_uint(kv.y);
            KPs[row][lcol + 2] = __float_as_uint(kv.z);
            KPs[row][lcol + 3] = __float_as_uint(kv.w);
            float4 vv = *(const float4*)(base + 2 * C_ + (size_t)(k0 + row) * C3_ + lcol);
            Vs[row][lcol + 0] = __float_as_uint(vv.x);
            Vs[row][lcol + 1] = __float_as_uint(vv.y);
            Vs[row][lcol + 2] = __float_as_uint(vv.z);
            Vs[row][lcol + 3] = __float_as_uint(vv.w);
        }
        __syncthreads();

        // ---- S = Q @ K^T ----
        float s[8][4];
#pragma unroll
        for (int nf = 0; nf < 8; nf++)
#pragma unroll
            for (int r = 0; r < 4; r++) s[nf][r] = 0.f;

#pragma unroll
        for (int ch = 0; ch < 8; ch++) {
            uint32_t bf0[8], bf1[8];
#pragma unroll
            for (int nf = 0; nf < 8; nf++) {
                bf0[nf] = KPs[nf * 8 + gid][ch * 8 + tq    ];
                bf1[nf] = KPs[nf * 8 + gid][ch * 8 + tq + 4];
            }
#pragma unroll
            for (int nf = 0; nf < 8; nf++)
                mma_tf32(s[nf], qa[ch], bf0[nf], bf1[nf]);
        }

        // ---- Causal mask on diagonal tile ----
        if (kt == qt) {
#pragma unroll
            for (int nf = 0; nf < 8; nf++) {
                int col = nf * 8 + 2 * tq;
                int row0 = qrow + gid, row1 = qrow + gid + 8;
                if (col     > row0) s[nf][0] = -1e30f;
                if (col + 1 > row0) s[nf][1] = -1e30f;
                if (col     > row1) s[nf][2] = -1e30f;
                if (col + 1 > row1) s[nf][3] = -1e30f;
            }
        }

        // ---- Online softmax ----
#pragma unroll
        for (int r = 0; r < 2; r++) {
            float mx = -1e30f;
#pragma unroll
            for (int nf = 0; nf < 8; nf++)
                mx = fmaxf(mx, fmaxf(s[nf][2 * r], s[nf][2 * r + 1]));
            mx = fmaxf(mx, __shfl_xor_sync(0xffffffffu, mx, 1));
            mx = fmaxf(mx, __shfl_xor_sync(0xffffffffu, mx, 2));
            float mnew = fmaxf(m_i[r], mx);
            float alpha = __expf(m_i[r] - mnew);
            float psum = 0.f;
#pragma unroll
            for (int nf = 0; nf < 8; nf++) {
                float p0 = __expf(s[nf][2 * r]     - mnew);
                float p1 = __expf(s[nf][2 * r + 1] - mnew);
                s[nf][2 * r]     = p0;
                s[nf][2 * r + 1] = p1;
                psum += p0 + p1;
            }
            psum += __shfl_xor_sync(0xffffffffu, psum, 1);
            psum += __shfl_xor_sync(0xffffffffu, psum, 2);
            l_i[r] = l_i[r] * alpha + psum;
            m_i[r] = mnew;
#pragma unroll
            for (int nf = 0; nf < 8; nf++) {
                o[nf][2 * r]     *= alpha;
                o[nf][2 * r + 1] *= alpha;
            }
        }

        // ---- Write P (tf32, fresh exp outputs need the cvt) into K buffer ----
        __syncthreads();
#pragma unroll
        for (int nf = 0; nf < 8; nf++) {
            int col = nf * 8 + 2 * tq;
            KPs[qrow + gid    ][col    ] = f2tf32(s[nf][0]);
            KPs[qrow + gid    ][col + 1] = f2tf32(s[nf][1]);
            KPs[qrow + gid + 8][col    ] = f2tf32(s[nf][2]);
            KPs[qrow + gid + 8][col + 1] = f2tf32(s[nf][3]);
        }
        __syncwarp();   // warp reads back only its own 16 rows

        // ---- O += P @ V ----
#pragma unroll
        for (int ch = 0; ch < 8; ch++) {
            uint32_t pa[4];
            pa[0] = KPs[qrow + gid    ][ch * 8 + tq    ];
            pa[1] = KPs[qrow + gid + 8][ch * 8 + tq    ];
            pa[2] = KPs[qrow + gid    ][ch * 8 + tq + 4];
            pa[3] = KPs[qrow + gid + 8][ch * 8 + tq + 4];
            uint32_t vb0[8], vb1[8];
#pragma unroll
            for (int nf = 0; nf < 8; nf++) {
                vb0[nf] = Vs[ch * 8 + tq    ][nf * 8 + gid];
                vb1[nf] = Vs[ch * 8 + tq + 4][nf * 8 + gid];
            }
#pragma unroll
            for (int nf = 0; nf < 8; nf++)
                mma_tf32(o[nf], pa, vb0[nf], vb1[nf]);
        }
        __syncthreads();   // before next K/V load overwrites KPs/Vs
    }

    // ---- Normalize + write y (tf32-rounded for the cvt-free proj GEMM) ----
#pragma unroll
    for (int r = 0; r < 2; r++) {
        float inv = 1.f / l_i[r];
        int row = q0 + qrow + gid + 8 * r;
        float* yb = g_y + (size_t)(b * T_ + row) * C_ + h * D_;
#pragma unroll
        for (int nf = 0; nf < 8; nf++) {
            float2 v;
            v.x = __uint_as_float(f2tf32(o[nf][2 * r]     * inv));
            v.y = __uint_as_float(f2tf32(o[nf][2 * r + 1] * inv));
            *(float2*)(yb + nf * 8 + 2 * tq) = v;
        }
    }
}

// ---------------------------------------------------------------------------
extern "C" void kernel_launch(void* const* d_in, const int* in_sizes, int n_in,
                              void* d_out, int out_size)
{
    const float* x      = (const float*)d_in[0];
    const float* W_attn = (const float*)d_in[1];
    const float* b_attn = (const float*)d_in[2];
    const float* W_proj = (const float*)d_in[3];
    const float* b_proj = (const float*)d_in[4];
    float* out = (float*)d_out;

    // 0) Boundary conversion to tf32 bits
    cvt_tf32_kernel<U_XA><<<(M_ * C_ / 4) / 256, 256>>>((const float4*)x, M_ * C_ / 4);
    cvt_tf32_kernel<U_WA><<<(C_ * C3_ / 4) / 256, 256>>>((const float4*)W_attn, C_ * C3_ / 4);
    cvt_tf32_kernel<U_WP><<<(C_ * C_ / 4) / 256, 256>>>((const float4*)W_proj, C_ * C_ / 4);

    // 1) QKV GEMM (cvt-free mainloop), epilogue stores tf32-rounded qkv
    gemm_tf32_kernel<U_XA, U_WA, D_QKV, true><<<dim3(C3_ / BN, M_ / BM), 256>>>(
        b_attn, nullptr, C_, C3_);
    // 2) Causal flash attention (raw-bit tf32 mma): g_qkv -> g_y (tf32-rounded)
    attn_tc_kernel<<<dim3(T_ / 64, B_ * H_), 128>>>();
    // 3) Output projection (cvt-free mainloop) -> out (full f32 epilogue)
    gemm_tf32_kernel<U_Y, U_WP, D_EXT, false><<<dim3(C_ / BN, M_ / BM), 256>>>(
        b_proj, out, C_, C_);
}

// round 8
// speedup vs baseline: 1.0259x; 1.0259x over previous
#include <cuda_runtime.h>
#include <cuda_bf16.h>
#include <cstdint>

// Problem shape (fixed): B=4, T=2048, C=1024, H=16, D=64
#define B_   4
#define T_   2048
#define C_   1024
#define H_   16
#define D_   64
#define M_   (B_ * T_)      // 8192 rows
#define C3_  (3 * C_)       // 3072

// Scratch (allocation-free rule: __device__ globals)
__device__ float    g_qkv[(size_t)M_ * C3_];  // 96 MB, values tf32-rounded
__device__ float    g_y[(size_t)M_ * C_];     // 32 MB, values tf32-rounded
__device__ uint32_t g_xa[(size_t)M_ * C_];    // 32 MB, x as tf32 bits
__device__ uint32_t g_wa[(size_t)C_ * C3_];   // 12 MB, W_attn as tf32 bits
__device__ uint32_t g_wp[(size_t)C_ * C_];    //  4 MB, W_proj as tf32 bits

// Buffer selectors
#define U_XA 0
#define U_WA 1
#define U_WP 2
#define U_Y  3
#define D_QKV 0
#define D_EXT 1

__device__ __forceinline__ uint32_t* resolve_u(int sel) {
    if (sel == U_XA) return g_xa;
    if (sel == U_WA) return g_wa;
    if (sel == U_WP) return g_wp;
    return reinterpret_cast<uint32_t*>(g_y);
}

__device__ __forceinline__ void cp_async16(void* smem_dst, const void* gmem_src) {
    uint32_t s = (uint32_t)__cvta_generic_to_shared(smem_dst);
    asm volatile("cp.async.cg.shared.global [%0], [%1], 16;\n" :: "r"(s), "l"(gmem_src));
}
__device__ __forceinline__ void cp_async_commit() {
    asm volatile("cp.async.commit_group;\n");
}
template <int N>
__device__ __forceinline__ void cp_async_wait_group_n() {
    asm volatile("cp.async.wait_group %0;\n" :: "n"(N));
}
__device__ __forceinline__ uint32_t f2tf32(float x) {
    uint32_t u;
    asm("cvt.rna.tf32.f32 %0, %1;\n" : "=r"(u) : "f"(x));
    return u;
}
__device__ __forceinline__ void mma_tf32(float* c, const uint32_t* a,
                                         uint32_t b0, uint32_t b1) {
    asm volatile(
        "mma.sync.aligned.m16n8k8.row.col.f32.tf32.tf32.f32 "
        "{%0,%1,%2,%3}, {%4,%5,%6,%7}, {%8,%9}, {%0,%1,%2,%3};\n"
        : "+f"(c[0]), "+f"(c[1]), "+f"(c[2]), "+f"(c[3])
        : "r"(a[0]), "r"(a[1]), "r"(a[2]), "r"(a[3]), "r"(b0), "r"(b1));
}

// ---------------------------------------------------------------------------
// Boundary converter: f32 -> tf32 bits (rna). Vectorized float4 -> uint4.
// ---------------------------------------------------------------------------
template <int OSEL>
__global__ __launch_bounds__(256) void cvt_tf32_kernel(const float4* __restrict__ in, int n4)
{
    uint32_t* out = resolve_u(OSEL);
    int i = blockIdx.x * blockDim.x + threadIdx.x;
    if (i < n4) {
        float4 v = in[i];
        uint4 u;
        u.x = f2tf32(v.x); u.y = f2tf32(v.y);
        u.z = f2tf32(v.z); u.w = f2tf32(v.w);
        reinterpret_cast<uint4*>(out)[i] = u;
    }
}

// ---------------------------------------------------------------------------
// TF32 tensor-core GEMM + bias, 4-stage cp.async pipeline, cvt-free mainloop.
// out[M,N] = A[M,K] @ W[K,N] + bias[N]. Dynamic smem (74KB).
// ---------------------------------------------------------------------------
#define BM 128
#define BN 128
#define BKT 16
#define A_STRIDE 20
#define B_STRIDE 136
#define STAGES 4
#define A_STAGE_ELEMS (BM * A_STRIDE)
#define B_STAGE_ELEMS (BKT * B_STRIDE)
#define GEMM_SMEM_BYTES ((STAGES * (A_STAGE_ELEMS + B_STAGE_ELEMS)) * 4)

template <int ASEL, int WSEL, int DSEL, bool ROUND>
__global__ __launch_bounds__(256) void gemm_tf32_kernel(
    const float* __restrict__ bias, float* __restrict__ out_ext,
    int K, int N)
{
    const uint32_t* A = resolve_u(ASEL);
    const uint32_t* W = resolve_u(WSEL);
    float* out = (DSEL == D_QKV) ? g_qkv : out_ext;

    extern __shared__ uint32_t smem[];
    uint32_t* As = smem;                               // [STAGES][BM][A_STRIDE]
    uint32_t* Bs = smem + STAGES * A_STAGE_ELEMS;      // [STAGES][BKT][B_STRIDE]

    const int tid  = threadIdx.x;
    const int warp = tid >> 5;
    const int lane = tid & 31;
    const int gid  = lane >> 2;
    const int tq   = lane & 3;

    const int warp_m = warp & 1;
    const int warp_n = warp >> 1;

    const int m0 = blockIdx.y * BM;
    const int n0 = blockIdx.x * BN;

    const int a_row0 = tid >> 2;
    const int a_kc0  = (tid & 3) * 4;
    const int b_row0 = tid >> 5;
    const int b_col0 = (tid & 31) * 4;

    float acc[4][4][4];
#pragma unroll
    for (int i = 0; i < 4; i++)
#pragma unroll
        for (int j = 0; j < 4; j++)
#pragma unroll
            for (int r = 0; r < 4; r++) acc[i][j][r] = 0.f;

    const int NT = K / BKT;

    auto load_tile = [&](int kt, int stg) {
        uint32_t* as = As + stg * A_STAGE_ELEMS;
        uint32_t* bs = Bs + stg * B_STAGE_ELEMS;
#pragma unroll
        for (int i = 0; i < 2; i++) {
            int row = a_row0 + i * 64;
            cp_async16(as + row * A_STRIDE + a_kc0,
                       A + (size_t)(m0 + row) * K + kt * BKT + a_kc0);
        }
#pragma unroll
        for (int i = 0; i < 2; i++) {
            int row = b_row0 + i * 8;
            cp_async16(bs + row * B_STRIDE + b_col0,
                       W + (size_t)(kt * BKT + row) * N + n0 + b_col0);
        }
        cp_async_commit();
    };

    // Prologue: prefetch 3 tiles (NT=64 >= 3 always here)
#pragma unroll
    for (int s = 0; s < STAGES - 1; s++) load_tile(s, s);

    for (int kt = 0; kt < NT; kt++) {
        // commits so far = 3 + kt; wait<2> => completed >= kt+1 => tile kt ready
        cp_async_wait_group_n<STAGES - 2>();
        __syncthreads();

        // Keep one commit per iteration (empty group past the end) so the
        // wait<2> arithmetic stays exact through the tail.
        if (kt + STAGES - 1 < NT) load_tile(kt + STAGES - 1, (kt + STAGES - 1) % STAGES);
        else                      cp_async_commit();

        const int stg = kt % STAGES;
        const uint32_t* as = As + stg * A_STAGE_ELEMS;
        const uint32_t* bs = Bs + stg * B_STAGE_ELEMS;

#pragma unroll
        for (int ks = 0; ks < BKT; ks += 8) {
            uint32_t af[4][4], bf[4][2];
#pragma unroll
            for (int mf = 0; mf < 4; mf++) {
                int mrow = warp_m * 64 + mf * 16;
                af[mf][0] = as[(mrow + gid    ) * A_STRIDE + ks + tq    ];
                af[mf][1] = as[(mrow + gid + 8) * A_STRIDE + ks + tq    ];
                af[mf][2] = as[(mrow + gid    ) * A_STRIDE + ks + tq + 4];
                af[mf][3] = as[(mrow + gid + 8) * A_STRIDE + ks + tq + 4];
            }
#pragma unroll
            for (int nf = 0; nf < 4; nf++) {
                int ncol = warp_n * 32 + nf * 8;
                bf[nf][0] = bs[(ks + tq    ) * B_STRIDE + ncol + gid];
                bf[nf][1] = bs[(ks + tq + 4) * B_STRIDE + ncol + gid];
            }
#pragma unroll
            for (int mf = 0; mf < 4; mf++)
#pragma unroll
                for (int nf = 0; nf < 4; nf++)
                    mma_tf32(acc[mf][nf], af[mf], bf[nf][0], bf[nf][1]);
        }
    }

#pragma unroll
    for (int nf = 0; nf < 4; nf++) {
        int colp = n0 + warp_n * 32 + nf * 8 + 2 * tq;
        float2 bb = *(const float2*)&bias[colp];
#pragma unroll
        for (int mf = 0; mf < 4; mf++) {
            int row0 = m0 + warp_m * 64 + mf * 16 + gid;
            float r00 = acc[mf][nf][0] + bb.x, r01 = acc[mf][nf][1] + bb.y;
            float r10 = acc[mf][nf][2] + bb.x, r11 = acc[mf][nf][3] + bb.y;
            if (ROUND) {
                r00 = __uint_as_float(f2tf32(r00));
                r01 = __uint_as_float(f2tf32(r01));
                r10 = __uint_as_float(f2tf32(r10));
                r11 = __uint_as_float(f2tf32(r11));
            }
            *(float2*)(out + (size_t)row0 * N + colp)       = make_float2(r00, r01);
            *(float2*)(out + (size_t)(row0 + 8) * N + colp) = make_float2(r10, r11);
        }
    }
}

// ---------------------------------------------------------------------------
// Tensor-core flash attention (causal). Unchanged.
// ---------------------------------------------------------------------------
#define AS_ 68

__global__ __launch_bounds__(128) void attn_tc_kernel()
{
    __shared__ uint32_t KPs[64][AS_];
    __shared__ uint32_t Vs[64][AS_];

    const int tid  = threadIdx.x;
    const int warp = tid >> 5;
    const int lane = tid & 31;
    const int gid  = lane >> 2;
    const int tq   = lane & 3;

    const int qt = gridDim.x - 1 - blockIdx.x;
    const int bh = blockIdx.y;
    const int b = bh >> 4, h = bh & 15;
    const int q0 = qt * 64;
    const int qrow = warp * 16;

    const int lrow = tid >> 4;
    const int lcol = (tid & 15) * 4;

    const float scale = 0.125f;
    const float* base = g_qkv + (size_t)(b * T_) * C3_ + h * D_;

#pragma unroll
    for (int p = 0; p < 8; p++) {
        int row = lrow + p * 8;
        float4 v = *(const float4*)(base + (size_t)(q0 + row) * C3_ + lcol);
        KPs[row][lcol + 0] = __float_as_uint(v.x * scale);
        KPs[row][lcol + 1] = __float_as_uint(v.y * scale);
        KPs[row][lcol + 2] = __float_as_uint(v.z * scale);
        KPs[row][lcol + 3] = __float_as_uint(v.w * scale);
    }
    __syncthreads();

    uint32_t qa[8][4];
#pragma unroll
    for (int ch = 0; ch < 8; ch++) {
        qa[ch][0] = KPs[qrow + gid    ][ch * 8 + tq    ];
        qa[ch][1] = KPs[qrow + gid + 8][ch * 8 + tq    ];
        qa[ch][2] = KPs[qrow + gid    ][ch * 8 + tq + 4];
        qa[ch][3] = KPs[qrow + gid + 8][ch * 8 + tq + 4];
    }
    __syncthreads();

    float m_i[2] = {-1e30f, -1e30f};
    float l_i[2] = {0.f, 0.f};
    float o[8][4];
#pragma unroll
    for (int nf = 0; nf < 8; nf++)
#pragma unroll
        for (int r = 0; r < 4; r++) o[nf][r] = 0.f;

    for (int kt = 0; kt <= qt; kt++) {
        const int k0 = kt * 64;
#pragma unroll
        for (int p = 0; p < 8; p++) {
            int row = lrow + p * 8;
            float4 kv = *(const float4*)(base + C_ + (size_t)(k0 + row) * C3_ + lcol);
            KPs[row][lcol + 0] = __float_as_uint(kv.x);
            KPs[row][lcol + 1] = __float_as_uint(kv.y);
            KPs[row][lcol + 2] = __float_as_uint(kv.z);
            KPs[row][lcol + 3] = __float_as_uint(kv.w);
            float4 vv = *(const float4*)(base + 2 * C_ + (size_t)(k0 + row) * C3_ + lcol);
            Vs[row][lcol + 0] = __float_as_uint(vv.x);
            Vs[row][lcol + 1] = __float_as_uint(vv.y);
            Vs[row][lcol + 2] = __float_as_uint(vv.z);
            Vs[row][lcol + 3] = __float_as_uint(vv.w);
        }
        __syncthreads();

        float s[8][4];
#pragma unroll
        for (int nf = 0; nf < 8; nf++)
#pragma unroll
            for (int r = 0; r < 4; r++) s[nf][r] = 0.f;

#pragma unroll
        for (int ch = 0; ch < 8; ch++) {
            uint32_t bf0[8], bf1[8];
#pragma unroll
            for (int nf = 0; nf < 8; nf++) {
                bf0[nf] = KPs[nf * 8 + gid][ch * 8 + tq    ];
                bf1[nf] = KPs[nf * 8 + gid][ch * 8 + tq + 4];
            }
#pragma unroll
            for (int nf = 0; nf < 8; nf++)
                mma_tf32(s[nf], qa[ch], bf0[nf], bf1[nf]);
        }

        if (kt == qt) {
#pragma unroll
            for (int nf = 0; nf < 8; nf++) {
                int col = nf * 8 + 2 * tq;
                int row0 = qrow + gid, row1 = qrow + gid + 8;
                if (col     > row0) s[nf][0] = -1e30f;
                if (col + 1 > row0) s[nf][1] = -1e30f;
                if (col     > row1) s[nf][2] = -1e30f;
                if (col + 1 > row1) s[nf][3] = -1e30f;
            }
        }

#pragma unroll
        for (int r = 0; r < 2; r++) {
            float mx = -1e30f;
#pragma unroll
            for (int nf = 0; nf < 8; nf++)
                mx = fmaxf(mx, fmaxf(s[nf][2 * r], s[nf][2 * r + 1]));
            mx = fmaxf(mx, __shfl_xor_sync(0xffffffffu, mx, 1));
            mx = fmaxf(mx, __shfl_xor_sync(0xffffffffu, mx, 2));
            float mnew = fmaxf(m_i[r], mx);
            float alpha = __expf(m_i[r] - mnew);
            float psum = 0.f;
#pragma unroll
            for (int nf = 0; nf < 8; nf++) {
                float p0 = __expf(s[nf][2 * r]     - mnew);
                float p1 = __expf(s[nf][2 * r + 1] - mnew);
                s[nf][2 * r]     = p0;
                s[nf][2 * r + 1] = p1;
                psum += p0 + p1;
            }
            psum += __shfl_xor_sync(0xffffffffu, psum, 1);
            psum += __shfl_xor_sync(0xffffffffu, psum, 2);
            l_i[r] = l_i[r] * alpha + psum;
            m_i[r] = mnew;
#pragma unroll
            for (int nf = 0; nf < 8; nf++) {
                o[nf][2 * r]     *= alpha;
                o[nf][2 * r + 1] *= alpha;
            }
        }

        __syncthreads();
#pragma unroll
        for (int nf = 0; nf < 8; nf++) {
            int col = nf * 8 + 2 * tq;
            KPs[qrow + gid    ][col    ] = f2tf32(s[nf][0]);
            KPs[qrow + gid    ][col + 1] = f2tf32(s[nf][1]);
            KPs[qrow + gid + 8][col    ] = f2tf32(s[nf][2]);
            KPs[qrow + gid + 8][col + 1] = f2tf32(s[nf][3]);
        }
        __syncwarp();

#pragma unroll
        for (int ch = 0; ch < 8; ch++) {
            uint32_t pa[4];
            pa[0] = KPs[qrow + gid    ][ch * 8 + tq    ];
            pa[1] = KPs[qrow + gid + 8][ch * 8 + tq    ];
            pa[2] = KPs[qrow + gid    ][ch * 8 + tq + 4];
            pa[3] = KPs[qrow + gid + 8][ch * 8 + tq + 4];
            uint32_t vb0[8], vb1[8];
#pragma unroll
            for (int nf = 0; nf < 8; nf++) {
                vb0[nf] = Vs[ch * 8 + tq    ][nf * 8 + gid];
                vb1[nf] = Vs[ch * 8 + tq + 4][nf * 8 + gid];
            }
#pragma unroll
            for (int nf = 0; nf < 8; nf++)
                mma_tf32(o[nf], pa, vb0[nf], vb1[nf]);
        }
        __syncthreads();
    }

#pragma unroll
    for (int r = 0; r < 2; r++) {
        float inv = 1.f / l_i[r];
        int row = q0 + qrow + gid + 8 * r;
        float* yb = g_y + (size_t)(b * T_ + row) * C_ + h * D_;
#pragma unroll
        for (int nf = 0; nf < 8; nf++) {
            float2 v;
            v.x = __uint_as_float(f2tf32(o[nf][2 * r]     * inv));
            v.y = __uint_as_float(f2tf32(o[nf][2 * r + 1] * inv));
            *(float2*)(yb + nf * 8 + 2 * tq) = v;
        }
    }
}

// ---------------------------------------------------------------------------
extern "C" void kernel_launch(void* const* d_in, const int* in_sizes, int n_in,
                              void* d_out, int out_size)
{
    const float* x      = (const float*)d_in[0];
    const float* W_attn = (const float*)d_in[1];
    const float* b_attn = (const float*)d_in[2];
    const float* W_proj = (const float*)d_in[3];
    const float* b_proj = (const float*)d_in[4];
    float* out = (float*)d_out;

    // Opt in to 74KB dynamic smem. Idempotent, called every invocation
    // (no static guards — kernel_launch behaves identically on every call).
    cudaFuncSetAttribute(gemm_tf32_kernel<U_XA, U_WA, D_QKV, true>,
                         cudaFuncAttributeMaxDynamicSharedMemorySize, GEMM_SMEM_BYTES);
    cudaFuncSetAttribute(gemm_tf32_kernel<U_Y, U_WP, D_EXT, false>,
                         cudaFuncAttributeMaxDynamicSharedMemorySize, GEMM_SMEM_BYTES);

    // 0) Boundary conversion to tf32 bits
    cvt_tf32_kernel<U_XA><<<(M_ * C_ / 4) / 256, 256>>>((const float4*)x, M_ * C_ / 4);
    cvt_tf32_kernel<U_WA><<<(C_ * C3_ / 4) / 256, 256>>>((const float4*)W_attn, C_ * C3_ / 4);
    cvt_tf32_kernel<U_WP><<<(C_ * C_ / 4) / 256, 256>>>((const float4*)W_proj, C_ * C_ / 4);

    // 1) QKV GEMM (4-stage pipeline) -> g_qkv (tf32-rounded)
    gemm_tf32_kernel<U_XA, U_WA, D_QKV, true>
        <<<dim3(C3_ / BN, M_ / BM), 256, GEMM_SMEM_BYTES>>>(b_attn, nullptr, C_, C3_);
    // 2) Causal flash attention: g_qkv -> g_y (tf32-rounded)
    attn_tc_kernel<<<dim3(T_ / 64, B_ * H_), 128>>>();
    // 3) Output projection (4-stage pipeline) -> out
    gemm_tf32_kernel<U_Y, U_WP, D_EXT, false>
        <<<dim3(C_ / BN, M_ / BM), 256, GEMM_SMEM_BYTES>>>(b_proj, out, C_, C_);
}

// round 10
// speedup vs baseline: 1.0441x; 1.0178x over previous
#include <cuda_runtime.h>
#include <cuda_bf16.h>
#include <cstdint>

// Problem shape (fixed): B=4, T=2048, C=1024, H=16, D=64
#define B_   4
#define T_   2048
#define C_   1024
#define H_   16
#define D_   64
#define M_   (B_ * T_)      // 8192 rows
#define C3_  (3 * C_)       // 3072

// Scratch (allocation-free rule: __device__ globals)
__device__ float    g_qkv[(size_t)M_ * C3_];  // 96 MB, values tf32-rounded
__device__ float    g_y[(size_t)M_ * C_];     // 32 MB, values tf32-rounded
__device__ uint32_t g_xa[(size_t)M_ * C_];    // 32 MB, x as tf32 bits
__device__ uint32_t g_wa[(size_t)C_ * C3_];   // 12 MB, W_attn as tf32 bits
__device__ uint32_t g_wp[(size_t)C_ * C_];    //  4 MB, W_proj as tf32 bits

// Buffer selectors
#define U_XA 0
#define U_WA 1
#define U_WP 2
#define U_Y  3
#define D_QKV 0
#define D_EXT 1

__device__ __forceinline__ uint32_t* resolve_u(int sel) {
    if (sel == U_XA) return g_xa;
    if (sel == U_WA) return g_wa;
    if (sel == U_WP) return g_wp;
    return reinterpret_cast<uint32_t*>(g_y);
}

__device__ __forceinline__ void cp_async16(void* smem_dst, const void* gmem_src) {
    uint32_t s = (uint32_t)__cvta_generic_to_shared(smem_dst);
    asm volatile("cp.async.cg.shared.global [%0], [%1], 16;\n" :: "r"(s), "l"(gmem_src));
}
__device__ __forceinline__ void cp_async_commit() {
    asm volatile("cp.async.commit_group;\n");
}
template <int N>
__device__ __forceinline__ void cp_async_wait_group_n() {
    asm volatile("cp.async.wait_group %0;\n" :: "n"(N));
}
__device__ __forceinline__ uint32_t f2tf32(float x) {
    uint32_t u;
    asm("cvt.rna.tf32.f32 %0, %1;\n" : "=r"(u) : "f"(x));
    return u;
}
__device__ __forceinline__ void mma_tf32(float* c, const uint32_t* a,
                                         uint32_t b0, uint32_t b1) {
    asm volatile(
        "mma.sync.aligned.m16n8k8.row.col.f32.tf32.tf32.f32 "
        "{%0,%1,%2,%3}, {%4,%5,%6,%7}, {%8,%9}, {%0,%1,%2,%3};\n"
        : "+f"(c[0]), "+f"(c[1]), "+f"(c[2]), "+f"(c[3])
        : "r"(a[0]), "r"(a[1]), "r"(a[2]), "r"(a[3]), "r"(b0), "r"(b1));
}

// ---------------------------------------------------------------------------
// Boundary converter: f32 -> tf32 bits (rna). Vectorized float4 -> uint4.
// ---------------------------------------------------------------------------
template <int OSEL>
__global__ __launch_bounds__(256) void cvt_tf32_kernel(const float4* __restrict__ in, int n4)
{
    uint32_t* out = resolve_u(OSEL);
    int i = blockIdx.x * blockDim.x + threadIdx.x;
    if (i < n4) {
        float4 v = in[i];
        uint4 u;
        u.x = f2tf32(v.x); u.y = f2tf32(v.y);
        u.z = f2tf32(v.z); u.w = f2tf32(v.w);
        reinterpret_cast<uint4*>(out)[i] = u;
    }
}

// ---------------------------------------------------------------------------
// TF32 tensor-core GEMM + bias, 4-stage cp.async smem pipeline PLUS
// register-level fragment double-buffering (cross-tile software pipeline).
// out[M,N] = A[M,K] @ W[K,N] + bias[N]. Dynamic smem (74KB).
// ---------------------------------------------------------------------------
#define BM 128
#define BN 128
#define BKT 16
#define A_STRIDE 20
#define B_STRIDE 136
#define STAGES 4
#define A_STAGE_ELEMS (BM * A_STRIDE)
#define B_STAGE_ELEMS (BKT * B_STRIDE)
#define GEMM_SMEM_BYTES ((STAGES * (A_STAGE_ELEMS + B_STAGE_ELEMS)) * 4)

template <int ASEL, int WSEL, int DSEL, bool ROUND>
__global__ __launch_bounds__(256, 2) void gemm_tf32_kernel(
    const float* __restrict__ bias, float* __restrict__ out_ext,
    int K, int N)
{
    const uint32_t* A = resolve_u(ASEL);
    const uint32_t* W = resolve_u(WSEL);
    float* out = (DSEL == D_QKV) ? g_qkv : out_ext;

    extern __shared__ uint32_t smem[];
    uint32_t* As = smem;                               // [STAGES][BM][A_STRIDE]
    uint32_t* Bs = smem + STAGES * A_STAGE_ELEMS;      // [STAGES][BKT][B_STRIDE]

    const int tid  = threadIdx.x;
    const int warp = tid >> 5;
    const int lane = tid & 31;
    const int gid  = lane >> 2;
    const int tq   = lane & 3;

    const int warp_m = warp & 1;
    const int warp_n = warp >> 1;

    const int m0 = blockIdx.y * BM;
    const int n0 = blockIdx.x * BN;

    const int a_row0 = tid >> 2;
    const int a_kc0  = (tid & 3) * 4;
    const int b_row0 = tid >> 5;
    const int b_col0 = (tid & 31) * 4;

    float acc[4][4][4];
#pragma unroll
    for (int i = 0; i < 4; i++)
#pragma unroll
        for (int j = 0; j < 4; j++)
#pragma unroll
            for (int r = 0; r < 4; r++) acc[i][j][r] = 0.f;

    const int NT = K / BKT;

    auto load_tile = [&](int kt, int stg) {
        uint32_t* as = As + stg * A_STAGE_ELEMS;
        uint32_t* bs = Bs + stg * B_STAGE_ELEMS;
#pragma unroll
        for (int i = 0; i < 2; i++) {
            int row = a_row0 + i * 64;
            cp_async16(as + row * A_STRIDE + a_kc0,
                       A + (size_t)(m0 + row) * K + kt * BKT + a_kc0);
        }
#pragma unroll
        for (int i = 0; i < 2; i++) {
            int row = b_row0 + i * 8;
            cp_async16(bs + row * B_STRIDE + b_col0,
                       W + (size_t)(kt * BKT + row) * N + n0 + b_col0);
        }
        cp_async_commit();
    };

    // Fragment double buffers (register-level pipeline)
    uint32_t af[2][4][4], bf[2][4][2];

    auto load_frags = [&](int stg, int ks, int pb) {
        const uint32_t* as = As + stg * A_STAGE_ELEMS;
        const uint32_t* bs = Bs + stg * B_STAGE_ELEMS;
#pragma unroll
        for (int mf = 0; mf < 4; mf++) {
            int mrow = warp_m * 64 + mf * 16;
            af[pb][mf][0] = as[(mrow + gid    ) * A_STRIDE + ks + tq    ];
            af[pb][mf][1] = as[(mrow + gid + 8) * A_STRIDE + ks + tq    ];
            af[pb][mf][2] = as[(mrow + gid    ) * A_STRIDE + ks + tq + 4];
            af[pb][mf][3] = as[(mrow + gid + 8) * A_STRIDE + ks + tq + 4];
        }
#pragma unroll
        for (int nf = 0; nf < 4; nf++) {
            int ncol = warp_n * 32 + nf * 8;
            bf[pb][nf][0] = bs[(ks + tq    ) * B_STRIDE + ncol + gid];
            bf[pb][nf][1] = bs[(ks + tq + 4) * B_STRIDE + ncol + gid];
        }
    };

    auto mma_group = [&](int pb) {
#pragma unroll
        for (int mf = 0; mf < 4; mf++)
#pragma unroll
            for (int nf = 0; nf < 4; nf++)
                mma_tf32(acc[mf][nf], af[pb][mf], bf[pb][nf][0], bf[pb][nf][1]);
    };

    // Prologue: prefetch 3 tiles; stage 0 ready -> preload its ks0 fragments.
#pragma unroll
    for (int s = 0; s < STAGES - 1; s++) load_tile(s, s);
    cp_async_wait_group_n<STAGES - 2>();
    __syncthreads();
    load_frags(0, 0, 0);

    for (int kt = 0; kt < NT; kt++) {
        // Frags for tile kt, ks=8 (overlaps with mma on ks=0 frags below)
        load_frags(kt % STAGES, 8, 1);
        mma_group(0);

        // commits = 3 + kt; wait<1> => tiles 0..kt+1 complete; barrier makes
        // them visible AND ensures everyone is done reading tile kt-1's stage
        // before we overwrite it.
        cp_async_wait_group_n<1>();
        __syncthreads();
        if (kt + STAGES - 1 < NT) load_tile(kt + STAGES - 1, (kt + STAGES - 1) % STAGES);
        else                      cp_async_commit();

        // Frags for tile kt+1, ks=0 (stage (kt+1)%4, distinct from the stage
        // just written, which is (kt+3)%4). Overlaps with mma on ks=8 frags.
        if (kt + 1 < NT) load_frags((kt + 1) % STAGES, 0, 0);
        mma_group(1);
    }

#pragma unroll
    for (int nf = 0; nf < 4; nf++) {
        int colp = n0 + warp_n * 32 + nf * 8 + 2 * tq;
        float2 bb = *(const float2*)&bias[colp];
#pragma unroll
        for (int mf = 0; mf < 4; mf++) {
            int row0 = m0 + warp_m * 64 + mf * 16 + gid;
            float r00 = acc[mf][nf][0] + bb.x, r01 = acc[mf][nf][1] + bb.y;
            float r10 = acc[mf][nf][2] + bb.x, r11 = acc[mf][nf][3] + bb.y;
            if (ROUND) {
                r00 = __uint_as_float(f2tf32(r00));
                r01 = __uint_as_float(f2tf32(r01));
                r10 = __uint_as_float(f2tf32(r10));
                r11 = __uint_as_float(f2tf32(r11));
            }
            *(float2*)(out + (size_t)row0 * N + colp)       = make_float2(r00, r01);
            *(float2*)(out + (size_t)(row0 + 8) * N + colp) = make_float2(r10, r11);
        }
    }
}

// ---------------------------------------------------------------------------
// Tensor-core flash attention (causal). Unchanged.
// ---------------------------------------------------------------------------
#define AS_ 68

__global__ __launch_bounds__(128) void attn_tc_kernel()
{
    __shared__ uint32_t KPs[64][AS_];
    __shared__ uint32_t Vs[64][AS_];

    const int tid  = threadIdx.x;
    const int warp = tid >> 5;
    const int lane = tid & 31;
    const int gid  = lane >> 2;
    const int tq   = lane & 3;

    const int qt = gridDim.x - 1 - blockIdx.x;
    const int bh = blockIdx.y;
    const int b = bh >> 4, h = bh & 15;
    const int q0 = qt * 64;
    const int qrow = warp * 16;

    const int lrow = tid >> 4;
    const int lcol = (tid & 15) * 4;

    const float scale = 0.125f;
    const float* base = g_qkv + (size_t)(b * T_) * C3_ + h * D_;

#pragma unroll
    for (int p = 0; p < 8; p++) {
        int row = lrow + p * 8;
        float4 v = *(const float4*)(base + (size_t)(q0 + row) * C3_ + lcol);
        KPs[row][lcol + 0] = __float_as_uint(v.x * scale);
        KPs[row][lcol + 1] = __float_as_uint(v.y * scale);
        KPs[row][lcol + 2] = __float_as_uint(v.z * scale);
        KPs[row][lcol + 3] = __float_as_uint(v.w * scale);
    }
    __syncthreads();

    uint32_t qa[8][4];
#pragma unroll
    for (int ch = 0; ch < 8; ch++) {
        qa[ch][0] = KPs[qrow + gid    ][ch * 8 + tq    ];
        qa[ch][1] = KPs[qrow + gid + 8][ch * 8 + tq    ];
        qa[ch][2] = KPs[qrow + gid    ][ch * 8 + tq + 4];
        qa[ch][3] = KPs[qrow + gid + 8][ch * 8 + tq + 4];
    }
    __syncthreads();

    float m_i[2] = {-1e30f, -1e30f};
    float l_i[2] = {0.f, 0.f};
    float o[8][4];
#pragma unroll
    for (int nf = 0; nf < 8; nf++)
#pragma unroll
        for (int r = 0; r < 4; r++) o[nf][r] = 0.f;

    for (int kt = 0; kt <= qt; kt++) {
        const int k0 = kt * 64;
#pragma unroll
        for (int p = 0; p < 8; p++) {
            int row = lrow + p * 8;
            float4 kv = *(const float4*)(base + C_ + (size_t)(k0 + row) * C3_ + lcol);
            KPs[row][lcol + 0] = __float_as_uint(kv.x);
            KPs[row][lcol + 1] = __float_as_uint(kv.y);
            KPs[row][lcol + 2] = __float_as_uint(kv.z);
            KPs[row][lcol + 3] = __float_as_uint(kv.w);
            float4 vv = *(const float4*)(base + 2 * C_ + (size_t)(k0 + row) * C3_ + lcol);
            Vs[row][lcol + 0] = __float_as_uint(vv.x);
            Vs[row][lcol + 1] = __float_as_uint(vv.y);
            Vs[row][lcol + 2] = __float_as_uint(vv.z);
            Vs[row][lcol + 3] = __float_as_uint(vv.w);
        }
        __syncthreads();

        float s[8][4];
#pragma unroll
        for (int nf = 0; nf < 8; nf++)
#pragma unroll
            for (int r = 0; r < 4; r++) s[nf][r] = 0.f;

#pragma unroll
        for (int ch = 0; ch < 8; ch++) {
            uint32_t bf0[8], bf1[8];
#pragma unroll
            for (int nf = 0; nf < 8; nf++) {
                bf0[nf] = KPs[nf * 8 + gid][ch * 8 + tq    ];
                bf1[nf] = KPs[nf * 8 + gid][ch * 8 + tq + 4];
            }
#pragma unroll
            for (int nf = 0; nf < 8; nf++)
                mma_tf32(s[nf], qa[ch], bf0[nf], bf1[nf]);
        }

        if (kt == qt) {
#pragma unroll
            for (int nf = 0; nf < 8; nf++) {
                int col = nf * 8 + 2 * tq;
                int row0 = qrow + gid, row1 = qrow + gid + 8;
                if (col     > row0) s[nf][0] = -1e30f;
                if (col + 1 > row0) s[nf][1] = -1e30f;
                if (col     > row1) s[nf][2] = -1e30f;
                if (col + 1 > row1) s[nf][3] = -1e30f;
            }
        }

#pragma unroll
        for (int r = 0; r < 2; r++) {
            float mx = -1e30f;
#pragma unroll
            for (int nf = 0; nf < 8; nf++)
                mx = fmaxf(mx, fmaxf(s[nf][2 * r], s[nf][2 * r + 1]));
            mx = fmaxf(mx, __shfl_xor_sync(0xffffffffu, mx, 1));
            mx = fmaxf(mx, __shfl_xor_sync(0xffffffffu, mx, 2));
            float mnew = fmaxf(m_i[r], mx);
            float alpha = __expf(m_i[r] - mnew);
            float psum = 0.f;
#pragma unroll
            for (int nf = 0; nf < 8; nf++) {
                float p0 = __expf(s[nf][2 * r]     - mnew);
                float p1 = __expf(s[nf][2 * r + 1] - mnew);
                s[nf][2 * r]     = p0;
                s[nf][2 * r + 1] = p1;
                psum += p0 + p1;
            }
            psum += __shfl_xor_sync(0xffffffffu, psum, 1);
            psum += __shfl_xor_sync(0xffffffffu, psum, 2);
            l_i[r] = l_i[r] * alpha + psum;
            m_i[r] = mnew;
#pragma unroll
            for (int nf = 0; nf < 8; nf++) {
                o[nf][2 * r]     *= alpha;
                o[nf][2 * r + 1] *= alpha;
            }
        }

        __syncthreads();
#pragma unroll
        for (int nf = 0; nf < 8; nf++) {
            int col = nf * 8 + 2 * tq;
            KPs[qrow + gid    ][col    ] = f2tf32(s[nf][0]);
            KPs[qrow + gid    ][col + 1] = f2tf32(s[nf][1]);
            KPs[qrow + gid + 8][col    ] = f2tf32(s[nf][2]);
            KPs[qrow + gid + 8][col + 1] = f2tf32(s[nf][3]);
        }
        __syncwarp();

#pragma unroll
        for (int ch = 0; ch < 8; ch++) {
            uint32_t pa[4];
            pa[0] = KPs[qrow + gid    ][ch * 8 + tq    ];
            pa[1] = KPs[qrow + gid + 8][ch * 8 + tq    ];
            pa[2] = KPs[qrow + gid    ][ch * 8 + tq + 4];
            pa[3] = KPs[qrow + gid + 8][ch * 8 + tq + 4];
            uint32_t vb0[8], vb1[8];
#pragma unroll
            for (int nf = 0; nf < 8; nf++) {
                vb0[nf] = Vs[ch * 8 + tq    ][nf * 8 + gid];
                vb1[nf] = Vs[ch * 8 + tq + 4][nf * 8 + gid];
            }
#pragma unroll
            for (int nf = 0; nf < 8; nf++)
                mma_tf32(o[nf], pa, vb0[nf], vb1[nf]);
        }
        __syncthreads();
    }

#pragma unroll
    for (int r = 0; r < 2; r++) {
        float inv = 1.f / l_i[r];
        int row = q0 + qrow + gid + 8 * r;
        float* yb = g_y + (size_t)(b * T_ + row) * C_ + h * D_;
#pragma unroll
        for (int nf = 0; nf < 8; nf++) {
            float2 v;
            v.x = __uint_as_float(f2tf32(o[nf][2 * r]     * inv));
            v.y = __uint_as_float(f2tf32(o[nf][2 * r + 1] * inv));
            *(float2*)(yb + nf * 8 + 2 * tq) = v;
        }
    }
}

// ---------------------------------------------------------------------------
extern "C" void kernel_launch(void* const* d_in, const int* in_sizes, int n_in,
                              void* d_out, int out_size)
{
    const float* x      = (const float*)d_in[0];
    const float* W_attn = (const float*)d_in[1];
    const float* b_attn = (const float*)d_in[2];
    const float* W_proj = (const float*)d_in[3];
    const float* b_proj = (const float*)d_in[4];
    float* out = (float*)d_out;

    // Opt in to 74KB dynamic smem. Idempotent, called every invocation.
    cudaFuncSetAttribute(gemm_tf32_kernel<U_XA, U_WA, D_QKV, true>,
                         cudaFuncAttributeMaxDynamicSharedMemorySize, GEMM_SMEM_BYTES);
    cudaFuncSetAttribute(gemm_tf32_kernel<U_Y, U_WP, D_EXT, false>,
                         cudaFuncAttributeMaxDynamicSharedMemorySize, GEMM_SMEM_BYTES);

    // 0) Boundary conversion to tf32 bits
    cvt_tf32_kernel<U_XA><<<(M_ * C_ / 4) / 256, 256>>>((const float4*)x, M_ * C_ / 4);
    cvt_tf32_kernel<U_WA><<<(C_ * C3_ / 4) / 256, 256>>>((const float4*)W_attn, C_ * C3_ / 4);
    cvt_tf32_kernel<U_WP><<<(C_ * C_ / 4) / 256, 256>>>((const float4*)W_proj, C_ * C_ / 4);

    // 1) QKV GEMM (smem + register pipelined) -> g_qkv (tf32-rounded)
    gemm_tf32_kernel<U_XA, U_WA, D_QKV, true>
        <<<dim3(C3_ / BN, M_ / BM), 256, GEMM_SMEM_BYTES>>>(b_attn, nullptr, C_, C3_);
    // 2) Causal flash attention: g_qkv -> g_y (tf32-rounded)
    attn_tc_kernel<<<dim3(T_ / 64, B_ * H_), 128>>>();
    // 3) Output projection (smem + register pipelined) -> out
    gemm_tf32_kernel<U_Y, U_WP, D_EXT, false>
        <<<dim3(C_ / BN, M_ / BM), 256, GEMM_SMEM_BYTES>>>(b_proj, out, C_, C_);
}